// round 7
// baseline (speedup 1.0000x reference)
#include <cuda_runtime.h>
#include <cstdint>
#include <cstddef>

#define B_PTS 256
#define DIM 128
#define N_BANK 500000
#define N_TILES 3907          /* ceil(500000/128) */
#define GRID_GEMM 148
#define THREADS 512
#define K2E 20.609929155556618f   /* log2(e)/0.07 */
#define PADF 132              /* padded floats per SMEM row (conflict-free frags) */

/* Schraudolph exp2: bitcast<float>((int)(s*K2E*2^23 + (127*2^23 - c))) ~= exp(s/T) */
#define SCHA 172888616.0f     /* K2E * 2^23 */
#define SCHB 1064992447.0f    /* 127*2^23 - 360769 */
#define SCHMAX 2130706432.0f  /* 0x7F000000 */

static __device__ float g_part[GRID_GEMM * B_PTS];
static __device__ int g_done = 0;

// ---------------- helpers ----------------
__device__ __forceinline__ uint32_t smem_u32(const void* p) {
    uint32_t a;
    asm("{ .reg .u64 t; cvta.to.shared.u64 t, %1; cvt.u32.u64 %0, t; }" : "=r"(a) : "l"(p));
    return a;
}
__device__ __forceinline__ float fast_ex2(float x) {
    float y; asm("ex2.approx.ftz.f32 %0, %1;" : "=f"(y) : "f"(x)); return y;
}
__device__ __forceinline__ float approx_expT(float s) {
    float t = fmaf(s, SCHA, SCHB);
    t = fmaxf(t, 0.0f);
    t = fminf(t, SCHMAX);
    return __int_as_float(__float2int_rn(t));
}
__device__ __forceinline__ void cp_async16(uint32_t dst, const void* src, int sz) {
    asm volatile("cp.async.cg.shared.global [%0], [%1], 16, %2;"
                 :: "r"(dst), "l"(src), "r"(sz) : "memory");
}
#define CP_COMMIT() asm volatile("cp.async.commit_group;" ::: "memory")
#define CP_WAIT3()  asm volatile("cp.async.wait_group 3;" ::: "memory")

// tf32 mma: D(16x8) += A(16x8) * B(8x8).  A row-major, B col-major.
__device__ __forceinline__ void mma_tf32(float c[4], const uint32_t a[4], const uint32_t b[2]) {
    asm volatile(
        "mma.sync.aligned.m16n8k8.row.col.f32.tf32.tf32.f32 "
        "{%0,%1,%2,%3}, {%4,%5,%6,%7}, {%8,%9}, {%0,%1,%2,%3};"
        : "+f"(c[0]), "+f"(c[1]), "+f"(c[2]), "+f"(c[3])
        : "r"(a[0]), "r"(a[1]), "r"(a[2]), "r"(a[3]), "r"(b[0]), "r"(b[1]));
}

// SMEM: A staging [256][132] fp32 == 4 B half-buffers [64][132] fp32 (reused).
#define SMEM_A_FLOATS (B_PTS * PADF)
#define SMEM_B_FLOATS (64 * PADF)
#define SMEM_TOTAL_BYTES (SMEM_A_FLOATS * 4)   /* == 4 * SMEM_B_FLOATS * 4 = 135168 */

__device__ __forceinline__ void load_half(const float* __restrict__ bank, float* sBh,
                                          int baserow, int tid) {
    #pragma unroll
    for (int it = 0; it < 4; it++) {
        int c = it * THREADS + tid;      // 2048 16B chunks (64 rows x 32 chunks)
        int r = c >> 5;
        int ch = c & 31;
        int grow = baserow + r;
        int ok = (grow < N_BANK);
        const float* src = bank + (size_t)(ok ? grow : 0) * DIM + ch * 4;
        uint32_t dst = smem_u32(sBh + r * PADF + ch * 4);
        cp_async16(dst, src, ok ? 16 : 0);
    }
}

// ---------------- single fused kernel ----------------
__global__ void __launch_bounds__(THREADS, 1)
hn_fused_kernel(const float* __restrict__ points, const int* __restrict__ pidx,
                const float* __restrict__ bank, float* __restrict__ out, int off) {
    extern __shared__ float sm[];
    float* sA = sm;                     // staging (reused as B buffers afterwards)

    const int tid = threadIdx.x;
    const int bid = blockIdx.x;
    const int wid = tid >> 5;           // 0..15, each warp owns 16 M-rows
    const int lane = tid & 31;
    const int grp = lane >> 2;          // 0..7
    const int tg = lane & 3;            // 0..3

    // ---- prologue: normalize points into sA (per-CTA; points is L2-hot) ----
    if (tid < B_PTS) {
        const int row = tid;
        const float4* src = reinterpret_cast<const float4*>(points) + row * 32;
        float ss = 0.0f;
        #pragma unroll 8
        for (int i = 0; i < 32; i++) {
            float4 q = src[i];
            ss += q.x * q.x + q.y * q.y + q.z * q.z + q.w * q.w;
        }
        float inv = rsqrtf(ss);
        float* dst = sA + row * PADF;
        #pragma unroll 8
        for (int i = 0; i < 32; i++) {
            float4 q = src[i];
            uint32_t ux, uy, uz, uw;
            asm("cvt.rna.tf32.f32 %0, %1;" : "=r"(ux) : "f"(q.x * inv));
            asm("cvt.rna.tf32.f32 %0, %1;" : "=r"(uy) : "f"(q.y * inv));
            asm("cvt.rna.tf32.f32 %0, %1;" : "=r"(uz) : "f"(q.z * inv));
            asm("cvt.rna.tf32.f32 %0, %1;" : "=r"(uw) : "f"(q.w * inv));
            dst[i * 4 + 0] = __uint_as_float(ux);
            dst[i * 4 + 1] = __uint_as_float(uy);
            dst[i * 4 + 2] = __uint_as_float(uz);
            dst[i * 4 + 3] = __uint_as_float(uw);
        }
    }
    __syncthreads();

    // ---- load this warp's A fragments into registers (tile-invariant) ----
    uint32_t a[16][4];
    {
        const uint32_t* Au = reinterpret_cast<const uint32_t*>(sA);
        const int r0 = (wid * 16 + grp) * PADF + tg;
        #pragma unroll
        for (int kt = 0; kt < 16; kt++) {
            const int base = r0 + kt * 8;
            a[kt][0] = Au[base];
            a[kt][1] = Au[base + 8 * PADF];
            a[kt][2] = Au[base + 4];
            a[kt][3] = Au[base + 8 * PADF + 4];
        }
    }
    __syncthreads();                    // A staging dead; SMEM becomes B pipeline

    // ---- 4-deep B pipeline prologue ----
    #pragma unroll
    for (int p = 0; p < 4; p++) {
        const int tile = bid + (p >> 1) * GRID_GEMM;
        load_half(bank, sm + (p & 3) * SMEM_B_FLOATS, tile * 128 + (p & 1) * 64, tid);
        CP_COMMIT();
    }

    const int halves = ((N_TILES - bid + GRID_GEMM - 1) / GRID_GEMM) * 2;

    // per-thread denominator partials: rows m0 = wid*16+grp and m0+8
    float accR0 = 0.f, accR1 = 0.f;
    const int m0 = wid * 16 + grp;
    float* const prow0 = out + off + (size_t)m0 * N_BANK;
    float* const prow1 = prow0 + (size_t)8 * N_BANK;

    for (int g = 0; g < halves; g++) {
        float* Bb = sm + (g & 3) * SMEM_B_FLOATS;
        CP_WAIT3();
        __syncthreads();

        const int tile = bid + (g >> 1) * GRID_GEMM;
        const int gnb = tile * 128 + (g & 1) * 64;    // global n base of this half
        int nv = N_BANK - gnb; if (nv > 64) nv = 64;

        float c[8][4];
        if (nv > 0) {
            #pragma unroll
            for (int nt = 0; nt < 8; nt++)
                #pragma unroll
                for (int q = 0; q < 4; q++) c[nt][q] = 0.f;

            const uint32_t* Bu = reinterpret_cast<const uint32_t*>(Bb);
            #pragma unroll 4
            for (int kt = 0; kt < 16; kt++) {
                const int kb = kt * 8 + tg;
                uint32_t b[8][2];
                #pragma unroll
                for (int nt = 0; nt < 8; nt++) {
                    const int bi = (nt * 8 + grp) * PADF + kb;
                    b[nt][0] = Bu[bi];
                    b[nt][1] = Bu[bi + 4];
                }
                #pragma unroll
                for (int nt = 0; nt < 8; nt++)
                    mma_tf32(c[nt], a[kt], b[nt]);
            }
        }

        __syncthreads();   // all warps done reading buffer g
        // ---- issue load for half g+4 into this buffer (overlaps epilogue) ----
        {
            const int g4 = g + 4;
            const int t4 = bid + (g4 >> 1) * GRID_GEMM;
            if (t4 < N_TILES)
                load_half(bank, sm + (g4 & 3) * SMEM_B_FLOATS,
                          t4 * 128 + (g4 & 1) * 64, tid);
            CP_COMMIT();
        }

        // ---- epilogue: Schraudolph exp-accumulate + store sims ----
        if (nv > 0) {
            #pragma unroll
            for (int nt = 0; nt < 8; nt++) {
                if (nt * 8 < nv) {                // nv is a multiple of 8
                    const int gn = gnb + nt * 8 + tg * 2;
                    float v0 = c[nt][0], v1 = c[nt][1];
                    float v2 = c[nt][2], v3 = c[nt][3];
                    accR0 += approx_expT(v0) + approx_expT(v1);
                    accR1 += approx_expT(v2) + approx_expT(v3);
                    prow0[gn] = v0; prow0[gn + 1] = v1;
                    prow1[gn] = v2; prow1[gn + 1] = v3;
                }
            }
        }
    }

    // ---- reduce denominator partials across the 4 lanes sharing a row ----
    accR0 += __shfl_xor_sync(0xFFFFFFFFu, accR0, 1);
    accR0 += __shfl_xor_sync(0xFFFFFFFFu, accR0, 2);
    accR1 += __shfl_xor_sync(0xFFFFFFFFu, accR1, 1);
    accR1 += __shfl_xor_sync(0xFFFFFFFFu, accR1, 2);
    if (tg == 0) {
        g_part[bid * B_PTS + m0] = accR0;
        g_part[bid * B_PTS + m0 + 8] = accR1;
    }

    // ---- last-CTA finalize ----
    __shared__ int s_last, s_is64;
    __shared__ float sh[B_PTS];
    __threadfence();
    if (tid == 0) s_last = (atomicAdd(&g_done, 1) == GRID_GEMM - 1);
    __syncthreads();
    if (!s_last) return;
    __threadfence();

    if (tid == 0) {
        int z = 1;
        for (int i = 1; i < 2 * B_PTS; i += 2)
            if (pidx[i] != 0) { z = 0; break; }
        s_is64 = z;
    }
    __syncthreads();

    if (tid < B_PTS) {
        const int b = tid;
        long long idx = s_is64 ? ((const long long*)pidx)[b] : (long long)pidx[b];
        float d = 0.0f;
        for (int c = 0; c < GRID_GEMM; c++) d += g_part[c * B_PTS + b];

        // exact fp32 positive similarity: dot(normalize(points[b]), bank[idx])
        const float4* pp = reinterpret_cast<const float4*>(points) + b * 32;
        const float4* bb = reinterpret_cast<const float4*>(bank) + (size_t)idx * 32;
        float ss = 0.0f, dp = 0.0f;
        #pragma unroll 8
        for (int i = 0; i < 32; i++) {
            float4 q = pp[i]; float4 r = bb[i];
            ss += q.x * q.x + q.y * q.y + q.z * q.z + q.w * q.w;
            dp += q.x * r.x + q.y * r.y + q.z * r.z + q.w * r.w;
        }
        float sim = dp * rsqrtf(ss);
        float pos = fast_ex2(sim * K2E);
        sh[b] = -logf(pos / d + 1e-7f);
    }
    __syncthreads();
    for (int o = 128; o > 0; o >>= 1) {
        if (tid < o) sh[tid] += sh[tid + o];
        __syncthreads();
    }
    if (tid == 0) {
        if (off) out[0] = sh[0] * (1.0f / 256.0f);
        g_done = 0;   // reset for next (graph-replayed) call: deterministic
    }
}

// ---------------- launch ----------------
extern "C" void kernel_launch(void* const* d_in, const int* in_sizes, int n_in,
                              void* d_out, int out_size) {
    const float* points = (const float*)d_in[0];
    const int* pidx = (const int*)d_in[1];
    const float* bank = (const float*)d_in[2];
    float* out = (float*)d_out;

    int off = (out_size > 128000000) ? 1 : 0;   // loss scalar precedes sims

    cudaFuncSetAttribute(hn_fused_kernel, cudaFuncAttributeMaxDynamicSharedMemorySize,
                         SMEM_TOTAL_BYTES);

    hn_fused_kernel<<<GRID_GEMM, THREADS, SMEM_TOTAL_BYTES>>>(points, pidx, bank, out, off);
}